// round 5
// baseline (speedup 1.0000x reference)
#include <cuda_runtime.h>

#define T 1024
#define BATCH 64
#define NBLK 768   // 3 branches * 64 batch * 4 sigma

__device__ float d_S2[4][3][BATCH];   // per-sigma, per-branch, per-batch partials
__device__ int   d_ctr;               // zero-initialized; finisher resets to 0

__device__ __forceinline__ float clamp01(float v) { return fminf(fmaxf(v, 0.f), 1.f); }

// ---------------------------------------------------------------------------
// 256-thread block reductions (8 warps)
// ---------------------------------------------------------------------------
__device__ __forceinline__ float blockMax256(float v, float* sRed) {
    int w = threadIdx.x >> 5, l = threadIdx.x & 31;
    #pragma unroll
    for (int off = 16; off; off >>= 1) v = fmaxf(v, __shfl_xor_sync(0xffffffffu, v, off));
    if (l == 0) sRed[w] = v;
    __syncthreads();
    if (threadIdx.x == 0) {
        float m = sRed[0];
        #pragma unroll
        for (int k = 1; k < 8; k++) m = fmaxf(m, sRed[k]);
        sRed[0] = m;
    }
    __syncthreads();
    float r = sRed[0];
    __syncthreads();
    return r;
}

__device__ __forceinline__ float blockSum256(float v, float* sRed) {
    int w = threadIdx.x >> 5, l = threadIdx.x & 31;
    #pragma unroll
    for (int off = 16; off; off >>= 1) v += __shfl_xor_sync(0xffffffffu, v, off);
    if (l == 0) sRed[w] = v;
    __syncthreads();
    if (threadIdx.x == 0) {
        float s = sRed[0];
        #pragma unroll
        for (int k = 1; k < 8; k++) s += sRed[k];
        sRed[0] = s;
    }
    __syncthreads();
    float r = sRed[0];
    __syncthreads();
    return r;
}

// ---------------------------------------------------------------------------
// One 16-wide i-tile: acc[ii] += sum over this lane's j-slice of
//   sA[j] * sGb[ii + j],  j = 4*lane + 128*k + jj, jj = 0..3, k = 0..K-1.
// All lanes share K and base -> no divergence; all LDS are 16B-lane-stride
// (conflict-free). 64 FMA + 6 LDS.128 per iteration.
// ---------------------------------------------------------------------------
__device__ __forceinline__ void tile16(const float* __restrict__ sA,
                                       const float* __restrict__ sGb,
                                       int K, int lane, float* __restrict__ acc)
{
    const float* ap = sA + 4 * lane;
    const float* gp = sGb + 4 * lane;
    for (int k = 0; k < K; k++) {
        float av[4];
        *(float4*)av = *(const float4*)ap;
        float gv[20];
        *(float4*)(gv + 0)  = *(const float4*)(gp + 0);
        *(float4*)(gv + 4)  = *(const float4*)(gp + 4);
        *(float4*)(gv + 8)  = *(const float4*)(gp + 8);
        *(float4*)(gv + 12) = *(const float4*)(gp + 12);
        *(float4*)(gv + 16) = *(const float4*)(gp + 16);
        #pragma unroll
        for (int ii = 0; ii < 16; ii++) {
            #pragma unroll
            for (int jj = 0; jj < 4; jj++)
                acc[ii] = fmaf(av[jj], gv[ii + jj], acc[ii]);
        }
        ap += 128;
        gp += 128;
    }
}

// ---------------------------------------------------------------------------
// Fused kernel. Block = (br, bb, sigma). Each warp owns ONE mirrored
// tile-pair: low tile i=16q.., high tile i=1008-16q.., q = sigma*8 + warp.
// K_low + K_high = 9 for every pair -> uniform warp work.
// ---------------------------------------------------------------------------
__global__ void __launch_bounds__(256) fused_kernel(
    const float* __restrict__ x1, const float* __restrict__ x2, const float* __restrict__ x3,
    const float* __restrict__ t1p, const float* __restrict__ b1p,
    const float* __restrict__ t2p, const float* __restrict__ b2p,
    const float* __restrict__ t3p, const float* __restrict__ b3p,
    const float* __restrict__ A1a, const float* __restrict__ A1b, const float* __restrict__ A1c,
    const float* __restrict__ A2a, const float* __restrict__ A2b, const float* __restrict__ A2c,
    const float* __restrict__ ba1, const float* __restrict__ ba2, const float* __restrict__ ba3,
    const float* __restrict__ bb1, const float* __restrict__ bb2, const float* __restrict__ bb3,
    const float* __restrict__ A4, const float* __restrict__ beta4p,
    float* __restrict__ out)
{
    __shared__ __align__(16) float sA[1152];     // softmax(A1), zeros beyond 1023
    __shared__ __align__(16) float sG[1184];     // sigmoid row, zeros beyond 1023
    __shared__ __align__(16) float sSuf[1024];   // inclusive suffix sums of sA
    __shared__ float sStage[8][16 * 33];         // per-warp reduce staging
    __shared__ float sW[256];                    // per-tile wb1 partial sums
    __shared__ float sRed[8];
    __shared__ float sWsum[8];
    __shared__ float sWexcl[8];
    __shared__ float sM2inv[2];                  // {A2 max, 1/A2 expsum}
    __shared__ float sBlk[256];
    __shared__ int   sDone;

    const float SIG10 = 4.5397868702434395e-05f; // sigmoid(-10) in fp32

    int bid = blockIdx.x;                 // br*256 + bb*4 + sigma
    int br = bid >> 8;
    int rem = bid & 255;
    int bb = rem >> 2;
    int sigma = rem & 3;

    const float* xs  = (br == 0) ? x1  : (br == 1) ? x2  : x3;
    const float* tp  = (br == 0) ? t1p : (br == 1) ? t2p : t3p;
    const float* bp  = (br == 0) ? b1p : (br == 1) ? b2p : b3p;
    const float* A1  = (br == 0) ? A1a : (br == 1) ? A1b : A1c;
    const float* A2  = (br == 0) ? A2a : (br == 1) ? A2b : A2c;
    const float* bap = (br == 0) ? ba1 : (br == 1) ? ba2 : ba3;

    int t = threadIdx.x;
    int w = t >> 5, l = t & 31;

    // ---------------- preamble: sigmoid row g ----------------
    float tv = tp[0];
    float bv = bp[0];
    {
        const float* xr = xs + bb * 1024;
        float4 xv = *(const float4*)(xr + 4 * t);
        float rr[4] = {xv.x, xv.y, xv.z, xv.w};
        float4 gvv;
        float* gp2 = (float*)&gvv;
        #pragma unroll
        for (int q = 0; q < 4; q++) {
            float prod = __fmul_rn(rr[q], tv);    // no contraction: exact r==b test
            float r = __fsub_rn(bv, prod);
            if (r == bv) r = -10.f;
            gp2[q] = __fdividef(1.f, 1.f + __expf(-r));
        }
        *(float4*)(sG + 4 * t) = gvv;
        if (t < 160) sG[1024 + t] = 0.f;
    }

    // ---------------- preamble: softmax(A1) + suffix scan ----------------
    {
        float4 v4 = *(const float4*)(A1 + 4 * t);
        float m = fmaxf(fmaxf(v4.x, v4.y), fmaxf(v4.z, v4.w));
        float M = blockMax256(m, sRed);
        float e0 = __expf(v4.x - M), e1 = __expf(v4.y - M);
        float e2 = __expf(v4.z - M), e3 = __expf(v4.w - M);
        float st = ((e0 + e1) + (e2 + e3));
        float SUM = blockSum256(st, sRed);
        float inv = __fdividef(1.f, SUM);
        float a0 = e0 * inv, a1 = e1 * inv, a2 = e2 * inv, a3 = e3 * inv;
        float4 av = {a0, a1, a2, a3};
        *(float4*)(sA + 4 * t) = av;
        if (t < 128) sA[1024 + t] = 0.f;

        // inclusive suffix scan over 4-element thread chunks
        float sn = ((a0 + a1) + (a2 + a3));
        float s = sn;
        #pragma unroll
        for (int off = 1; off < 32; off <<= 1) {
            float o = __shfl_down_sync(0xffffffffu, s, off);
            if (l + off < 32) s += o;
        }
        if (l == 0) sWsum[w] = s;
        __syncthreads();
        if (t < 8) {
            float tot = 0.f;
            for (int k = t + 1; k < 8; k++) tot += sWsum[k];
            sWexcl[t] = tot;
        }
        __syncthreads();
        float after = (s - sn) + sWexcl[w];   // strictly-after my chunk
        float v3s = after + a3;
        float v2s = v3s + a2;
        float v1s = v2s + a1;
        float v0s = v1s + a0;
        sSuf[4 * t + 3] = v3s;
        sSuf[4 * t + 2] = v2s;
        sSuf[4 * t + 1] = v1s;
        sSuf[4 * t + 0] = v0s;
    }

    // ---------------- preamble: softmax(A2) max & sum ----------------
    {
        float4 v4 = *(const float4*)(A2 + 4 * t);
        float m = fmaxf(fmaxf(v4.x, v4.y), fmaxf(v4.z, v4.w));
        float M2 = blockMax256(m, sRed);
        float st = __expf(v4.x - M2) + __expf(v4.y - M2)
                 + __expf(v4.z - M2) + __expf(v4.w - M2);
        float S2 = blockSum256(st, sRed);
        if (t == 0) { sM2inv[0] = M2; sM2inv[1] = __fdividef(1.f, S2); }
    }
    __syncthreads();

    // ---------------- main triangular correlation ----------------
    // Warp w owns pair q = sigma*8 + w. Low tile i = 16q..16q+15,
    // high tile i = 1008-16q..1008-16q+15. K_low + K_high = 9.
    float* st = &sStage[w][0];
    {
        int q = sigma * 8 + w;
        int bL = 16 * q;
        int bH = 1008 - 16 * q;

        #pragma unroll
        for (int hv = 0; hv < 2; hv++) {
            int base = hv ? bH : bL;
            int N = 1024 - base;
            int K = (N + 127) >> 7;

            float acc[16];
            #pragma unroll
            for (int ii = 0; ii < 16; ii++) acc[ii] = 0.f;

            tile16(sA, sG + base, K, l, acc);

            // warp-local reduction of 16 accs over 32 lanes
            #pragma unroll
            for (int ii = 0; ii < 16; ii++) st[ii * 33 + l] = acc[ii];
            __syncwarp();
            {
                int r = l >> 1, h = l & 1;   // lane -> (row r, half h)
                float s = 0.f;
                const float* row = st + r * 33 + 16 * h;
                #pragma unroll
                for (int k2 = 0; k2 < 16; k2++) s += row[k2];
                s += __shfl_xor_sync(0xffffffffu, s, 1);
                if (h == 0) sW[(w * 2 + hv) * 16 + r] = s;
            }
            __syncwarp();
        }
    }
    __syncthreads();

    // ---------------- epilogue: tail, clip, A2-weight ----------------
    float local;
    {
        float ba = bap[0];
        float M2 = sM2inv[0], invS2 = sM2inv[1];
        int slot = t >> 4;             // 0..15 = warp*2 + hv
        int ii = t & 15;
        int wq = slot >> 1;
        int hi = slot & 1;
        int q = sigma * 8 + wq;
        int i = hi ? (1008 - 16 * q + ii) : (16 * q + ii);
        float ssuf = (i == 0) ? 0.f : sSuf[1024 - i];
        float wb1 = sW[t] + (1.f - ba) + SIG10 * ssuf;
        float act = clamp01(wb1);
        float a2sm = __expf(A2[i] - M2) * invS2;
        local = a2sm * (1.f - act);
    }
    sBlk[t] = local;
    __syncthreads();
    #pragma unroll
    for (int s = 128; s > 0; s >>= 1) {
        if (t < s) sBlk[t] += sBlk[t + s];
        __syncthreads();
    }
    if (t == 0) d_S2[sigma][br][bb] = sBlk[0];

    // ---------------- last-block final combine ----------------
    __threadfence();
    if (t == 0) {
        int v = atomicAdd(&d_ctr, 1);
        sDone = (v == NBLK - 1) ? 1 : 0;
    }
    __syncthreads();
    if (sDone) {
        if (t < BATCH) {
            float e0 = __expf(A4[0]), e1 = __expf(A4[1]), e2 = __expf(A4[2]);
            float sinv = __fdividef(1.f, e0 + e1 + e2);
            float a40 = e0 * sinv, a41 = e1 * sinv, a42 = e2 * sinv;

            volatile float* vs = (volatile float*)d_S2;
            // d_S2[sigma][br][b] -> vs[sigma*192 + br*64 + b]
            float S0 = 0.f, S1 = 0.f, S2 = 0.f;
            #pragma unroll
            for (int sg = 0; sg < 4; sg++) {
                S0 += vs[sg * 192 + 0 * 64 + t];
                S1 += vs[sg * 192 + 1 * 64 + t];
                S2 += vs[sg * 192 + 2 * 64 + t];
            }
            float r0 = clamp01(bb1[0] - S0);
            float r1 = clamp01(bb2[0] - S1);
            float r2 = clamp01(bb3[0] - S2);
            float acc4 = beta4p[0];
            acc4 -= a40 * (1.f - r0);
            acc4 -= a41 * (1.f - r1);
            acc4 -= a42 * (1.f - r2);
            out[t] = clamp01(acc4);
        }
        if (t == 0) d_ctr = 0;   // reset for next graph replay
    }
}

extern "C" void kernel_launch(void* const* d_in, const int* in_sizes, int n_in,
                              void* d_out, int out_size)
{
    const float* x1      = (const float*)d_in[0];
    const float* x2      = (const float*)d_in[1];
    const float* x3      = (const float*)d_in[2];
    const float* t1      = (const float*)d_in[3];
    const float* b1      = (const float*)d_in[4];
    const float* A1_1    = (const float*)d_in[5];
    const float* A2_1    = (const float*)d_in[6];
    const float* beta1_1 = (const float*)d_in[7];
    const float* beta1_2 = (const float*)d_in[8];
    const float* t2      = (const float*)d_in[9];
    const float* b2      = (const float*)d_in[10];
    const float* A1_2    = (const float*)d_in[11];
    const float* A2_2    = (const float*)d_in[12];
    const float* beta2_1 = (const float*)d_in[13];
    const float* beta2_2 = (const float*)d_in[14];
    const float* t3      = (const float*)d_in[15];
    const float* b3      = (const float*)d_in[16];
    const float* A1_3    = (const float*)d_in[17];
    const float* A2_3    = (const float*)d_in[18];
    const float* beta3_1 = (const float*)d_in[19];
    const float* beta3_2 = (const float*)d_in[20];
    const float* A4      = (const float*)d_in[21];
    const float* beta4   = (const float*)d_in[22];
    float* out = (float*)d_out;

    fused_kernel<<<NBLK, 256>>>(x1, x2, x3,
                                t1, b1, t2, b2, t3, b3,
                                A1_1, A1_2, A1_3,
                                A2_1, A2_2, A2_3,
                                beta1_1, beta2_1, beta3_1,
                                beta1_2, beta2_2, beta3_2,
                                A4, beta4, out);
}

// round 7
// speedup vs baseline: 1.0133x; 1.0133x over previous
#include <cuda_runtime.h>

#define T 1024
#define BATCH 64
#define NBLK 384   // 3 branches * 64 batch * 2 sigma

__device__ float d_S2[2][3][BATCH];   // per-sigma, per-branch, per-batch partials
__device__ int   d_ctr;               // zero-initialized; finisher resets to 0

typedef unsigned long long ull;

__device__ __forceinline__ float clamp01(float v) { return fminf(fmaxf(v, 0.f), 1.f); }

#define FMA2(d, a, b) asm("fma.rn.f32x2 %0, %1, %2, %0;" : "+l"(d) : "l"(a), "l"(b))
#define PKF2(d, lo, hi) asm("mov.b64 %0, {%1, %2};" : "=l"(d) : "f"(lo), "f"(hi))
#define UPKF2(lo, hi, v) asm("mov.b64 {%0, %1}, %2;" : "=f"(lo), "=f"(hi) : "l"(v))

// ---------------------------------------------------------------------------
// Fused 2-value block reductions (256 threads, 8 warps)
// ---------------------------------------------------------------------------
__device__ __forceinline__ void blockMax2(float& a, float& b, float* sRA, float* sRB) {
    int w = threadIdx.x >> 5, l = threadIdx.x & 31;
    #pragma unroll
    for (int off = 16; off; off >>= 1) {
        a = fmaxf(a, __shfl_xor_sync(0xffffffffu, a, off));
        b = fmaxf(b, __shfl_xor_sync(0xffffffffu, b, off));
    }
    if (l == 0) { sRA[w] = a; sRB[w] = b; }
    __syncthreads();
    if (threadIdx.x == 0) {
        float ma = sRA[0], mb = sRB[0];
        #pragma unroll
        for (int k = 1; k < 8; k++) { ma = fmaxf(ma, sRA[k]); mb = fmaxf(mb, sRB[k]); }
        sRA[0] = ma; sRB[0] = mb;
    }
    __syncthreads();
    a = sRA[0]; b = sRB[0];
    __syncthreads();
}

__device__ __forceinline__ void blockSum2(float& a, float& b, float* sRA, float* sRB) {
    int w = threadIdx.x >> 5, l = threadIdx.x & 31;
    #pragma unroll
    for (int off = 16; off; off >>= 1) {
        a += __shfl_xor_sync(0xffffffffu, a, off);
        b += __shfl_xor_sync(0xffffffffu, b, off);
    }
    if (l == 0) { sRA[w] = a; sRB[w] = b; }
    __syncthreads();
    if (threadIdx.x == 0) {
        float sa = sRA[0], sb = sRB[0];
        #pragma unroll
        for (int k = 1; k < 8; k++) { sa += sRA[k]; sb += sRB[k]; }
        sRA[0] = sa; sRB[0] = sb;
    }
    __syncthreads();
    a = sRA[0]; b = sRB[0];
    __syncthreads();
}

// ---------------------------------------------------------------------------
// Packed 16-wide i-tile. Per k-iteration: 6 LDS.128, 4 broadcast packs,
// 34 fma.rn.f32x2. Dual accumulator banks, both built from even-aligned
// gv pairs GE[m] = (gv[2m], gv[2m+1]):
//   bankE[r] = (acc[2r],   acc[2r+1])  += av0*GE[r]   + av2*GE[r+1]   (jj=0,2)
//   bankO[m] = (acc[2m-1], acc[2m])    += av1*GE[m]   + av3*GE[m+1]   (jj=1,3)
// bankO[0].lo is a dummy (acc[-1]); bankO[8].hi is a dummy (acc[16]).
// ---------------------------------------------------------------------------
__device__ __forceinline__ void tile16p(const float* __restrict__ sA,
                                        const float* __restrict__ sGb,
                                        int K, int lane,
                                        ull* __restrict__ bankE,
                                        ull* __restrict__ bankO)
{
    const float* ap = sA + 4 * lane;
    const float* gp = sGb + 4 * lane;
    for (int k = 0; k < K; k++) {
        longlong2 g0 = *(const longlong2*)(gp + 0);
        longlong2 g1 = *(const longlong2*)(gp + 4);
        longlong2 g2 = *(const longlong2*)(gp + 8);
        longlong2 g3 = *(const longlong2*)(gp + 12);
        longlong2 g4 = *(const longlong2*)(gp + 16);
        ull GE[10];
        GE[0] = (ull)g0.x; GE[1] = (ull)g0.y;
        GE[2] = (ull)g1.x; GE[3] = (ull)g1.y;
        GE[4] = (ull)g2.x; GE[5] = (ull)g2.y;
        GE[6] = (ull)g3.x; GE[7] = (ull)g3.y;
        GE[8] = (ull)g4.x; GE[9] = (ull)g4.y;

        float4 av = *(const float4*)ap;
        ull AV0, AV1, AV2, AV3;
        PKF2(AV0, av.x, av.x);
        PKF2(AV1, av.y, av.y);
        PKF2(AV2, av.z, av.z);
        PKF2(AV3, av.w, av.w);

        #pragma unroll
        for (int r = 0; r < 8; r++) {
            FMA2(bankE[r], AV0, GE[r]);
            FMA2(bankE[r], AV2, GE[r + 1]);
        }
        #pragma unroll
        for (int m = 0; m < 9; m++) {
            FMA2(bankO[m], AV1, GE[m]);
            FMA2(bankO[m], AV3, GE[m + 1]);
        }
        ap += 128;
        gp += 128;
    }
}

// ---------------------------------------------------------------------------
// Fused kernel. Block = (br, bb, sigma in {0,1}); each of 8 warps owns 2
// mirrored tile-pairs (q = sigma*16 + 2w + pp).
// ---------------------------------------------------------------------------
__global__ void __launch_bounds__(256) fused_kernel(
    const float* __restrict__ x1, const float* __restrict__ x2, const float* __restrict__ x3,
    const float* __restrict__ t1p, const float* __restrict__ b1p,
    const float* __restrict__ t2p, const float* __restrict__ b2p,
    const float* __restrict__ t3p, const float* __restrict__ b3p,
    const float* __restrict__ A1a, const float* __restrict__ A1b, const float* __restrict__ A1c,
    const float* __restrict__ A2a, const float* __restrict__ A2b, const float* __restrict__ A2c,
    const float* __restrict__ ba1, const float* __restrict__ ba2, const float* __restrict__ ba3,
    const float* __restrict__ bb1, const float* __restrict__ bb2, const float* __restrict__ bb3,
    const float* __restrict__ A4, const float* __restrict__ beta4p,
    float* __restrict__ out)
{
    __shared__ __align__(16) float sA[1152];     // softmax(A1), zeros beyond 1023
    __shared__ __align__(16) float sG[1184];     // sigmoid row, zeros beyond 1023
    __shared__ __align__(16) float sSuf[1024];   // inclusive suffix sums of sA
    __shared__ __align__(16) float sA2[1024];    // softmax(A2)
    __shared__ float sStage[8][16 * 33];         // per-warp reduce staging
    __shared__ float sW[512];                    // per-tile wb1 partial sums
    __shared__ float sRA[8], sRB[8];
    __shared__ float sWsum[8];
    __shared__ float sWexcl[8];
    __shared__ float sBlk[256];
    __shared__ int   sDone;

    const float SIG10 = 4.5397868702434395e-05f; // sigmoid(-10) in fp32

    int bid = blockIdx.x;                 // br*128 + bb*2 + sigma
    int br = bid >> 7;
    int rem = bid & 127;
    int bb = rem >> 1;
    int sigma = rem & 1;

    const float* xs  = (br == 0) ? x1  : (br == 1) ? x2  : x3;
    const float* tp  = (br == 0) ? t1p : (br == 1) ? t2p : t3p;
    const float* bp  = (br == 0) ? b1p : (br == 1) ? b2p : b3p;
    const float* A1  = (br == 0) ? A1a : (br == 1) ? A1b : A1c;
    const float* A2  = (br == 0) ? A2a : (br == 1) ? A2b : A2c;
    const float* bap = (br == 0) ? ba1 : (br == 1) ? ba2 : ba3;

    int t = threadIdx.x;
    int w = t >> 5, l = t & 31;

    // ---------------- preamble: sigmoid row g ----------------
    float tv = tp[0];
    float bv = bp[0];
    {
        const float* xr = xs + bb * 1024;
        float4 xv = *(const float4*)(xr + 4 * t);
        float rr[4] = {xv.x, xv.y, xv.z, xv.w};
        float4 gvv;
        float* gp2 = (float*)&gvv;
        #pragma unroll
        for (int q = 0; q < 4; q++) {
            float prod = __fmul_rn(rr[q], tv);    // no contraction: exact r==b test
            float r = __fsub_rn(bv, prod);
            if (r == bv) r = -10.f;
            gp2[q] = __fdividef(1.f, 1.f + __expf(-r));
        }
        *(float4*)(sG + 4 * t) = gvv;
        if (t < 160) sG[1024 + t] = 0.f;
    }

    // ---------------- preamble: fused softmax(A1) & softmax(A2) ----------------
    float4 v1 = *(const float4*)(A1 + 4 * t);
    float4 v2 = *(const float4*)(A2 + 4 * t);
    {
        float m1 = fmaxf(fmaxf(v1.x, v1.y), fmaxf(v1.z, v1.w));
        float m2 = fmaxf(fmaxf(v2.x, v2.y), fmaxf(v2.z, v2.w));
        blockMax2(m1, m2, sRA, sRB);

        float e10 = __expf(v1.x - m1), e11 = __expf(v1.y - m1);
        float e12 = __expf(v1.z - m1), e13 = __expf(v1.w - m1);
        float e20 = __expf(v2.x - m2), e21 = __expf(v2.y - m2);
        float e22 = __expf(v2.z - m2), e23 = __expf(v2.w - m2);
        float s1 = (e10 + e11) + (e12 + e13);
        float s2 = (e20 + e21) + (e22 + e23);
        blockSum2(s1, s2, sRA, sRB);
        float inv1 = __fdividef(1.f, s1);
        float inv2 = __fdividef(1.f, s2);

        float a0 = e10 * inv1, a1 = e11 * inv1, a2 = e12 * inv1, a3 = e13 * inv1;
        float4 av = {a0, a1, a2, a3};
        *(float4*)(sA + 4 * t) = av;
        if (t < 128) sA[1024 + t] = 0.f;

        float4 a2v = {e20 * inv2, e21 * inv2, e22 * inv2, e23 * inv2};
        *(float4*)(sA2 + 4 * t) = a2v;

        // inclusive suffix scan of softmax(A1) over 4-element thread chunks
        float sn = ((a0 + a1) + (a2 + a3));
        float s = sn;
        #pragma unroll
        for (int off = 1; off < 32; off <<= 1) {
            float o = __shfl_down_sync(0xffffffffu, s, off);
            if (l + off < 32) s += o;
        }
        if (l == 0) sWsum[w] = s;
        __syncthreads();
        if (t < 8) {
            float tot = 0.f;
            for (int k = t + 1; k < 8; k++) tot += sWsum[k];
            sWexcl[t] = tot;
        }
        __syncthreads();
        float after = (s - sn) + sWexcl[w];   // strictly-after my chunk
        float v3s = after + a3;
        float v2s = v3s + a2;
        float v1s = v2s + a1;
        float v0s = v1s + a0;
        sSuf[4 * t + 3] = v3s;
        sSuf[4 * t + 2] = v2s;
        sSuf[4 * t + 1] = v1s;
        sSuf[4 * t + 0] = v0s;
    }
    __syncthreads();

    // ---------------- main triangular correlation ----------------
    // Warp w handles local pairs lp = 2w, 2w+1. Global pair q = sigma*16+lp.
    float* st = &sStage[w][0];
    #pragma unroll
    for (int pp = 0; pp < 2; pp++) {
        int lp = 2 * w + pp;
        int q = sigma * 16 + lp;
        int bL = 16 * q;
        int bH = 1008 - 16 * q;

        #pragma unroll
        for (int hv = 0; hv < 2; hv++) {
            int base = hv ? bH : bL;
            int N = 1024 - base;
            int K = (N + 127) >> 7;

            ull bankE[8], bankO[9];
            #pragma unroll
            for (int r = 0; r < 8; r++) bankE[r] = 0ULL;
            #pragma unroll
            for (int m = 0; m < 9; m++) bankO[m] = 0ULL;

            tile16p(sA, sG + base, K, l, bankE, bankO);

            // unpack + merge banks into 16 scalar accs
            float accf[16];
            #pragma unroll
            for (int r = 0; r < 8; r++) {
                float lo, hi;
                UPKF2(lo, hi, bankE[r]);
                accf[2 * r] = lo;
                accf[2 * r + 1] = hi;
            }
            #pragma unroll
            for (int m = 0; m < 9; m++) {
                float lo, hi;
                UPKF2(lo, hi, bankO[m]);
                if (m > 0) accf[2 * m - 1] += lo;   // m=0: acc[-1] dummy
                if (m < 8) accf[2 * m] += hi;       // m=8: acc[16] dummy
            }

            // warp-local reduction of 16 accs over 32 lanes
            #pragma unroll
            for (int ii = 0; ii < 16; ii++) st[ii * 33 + l] = accf[ii];
            __syncwarp();
            {
                int r = l >> 1, h = l & 1;   // lane -> (row r, half h)
                float s = 0.f;
                const float* row = st + r * 33 + 16 * h;
                #pragma unroll
                for (int k2 = 0; k2 < 16; k2++) s += row[k2];
                s += __shfl_xor_sync(0xffffffffu, s, 1);
                if (h == 0) sW[(lp * 2 + hv) * 16 + r] = s;
            }
            __syncwarp();
        }
    }
    __syncthreads();

    // ---------------- epilogue: tail, clip, A2-weight ----------------
    float local = 0.f;
    {
        float ba = bap[0];
        #pragma unroll
        for (int h = 0; h < 2; h++) {
            int v = 2 * t + h;            // 0..511
            int slot = v >> 4;            // 0..31 = lp*2 + hv
            int ii = v & 15;
            int lp = slot >> 1;
            int hi = slot & 1;
            int q = sigma * 16 + lp;
            int i = hi ? (1008 - 16 * q + ii) : (16 * q + ii);
            float ssuf = (i == 0) ? 0.f : sSuf[1024 - i];
            float wb1 = sW[v] + (1.f - ba) + SIG10 * ssuf;
            float act = clamp01(wb1);
            local += sA2[i] * (1.f - act);
        }
    }
    sBlk[t] = local;
    __syncthreads();
    #pragma unroll
    for (int s = 128; s > 0; s >>= 1) {
        if (t < s) sBlk[t] += sBlk[t + s];
        __syncthreads();
    }
    if (t == 0) d_S2[sigma][br][bb] = sBlk[0];

    // ---------------- last-block final combine ----------------
    __threadfence();
    if (t == 0) {
        int v = atomicAdd(&d_ctr, 1);
        sDone = (v == NBLK - 1) ? 1 : 0;
    }
    __syncthreads();
    if (sDone) {
        if (t < BATCH) {
            float e0 = __expf(A4[0]), e1 = __expf(A4[1]), e2 = __expf(A4[2]);
            float sinv = __fdividef(1.f, e0 + e1 + e2);
            float a40 = e0 * sinv, a41 = e1 * sinv, a42 = e2 * sinv;

            volatile float* vs = (volatile float*)d_S2;
            // d_S2[sigma][br][b] -> vs[sigma*192 + br*64 + b]
            float S0 = vs[0 * 192 + 0 * 64 + t] + vs[1 * 192 + 0 * 64 + t];
            float S1 = vs[0 * 192 + 1 * 64 + t] + vs[1 * 192 + 1 * 64 + t];
            float S2 = vs[0 * 192 + 2 * 64 + t] + vs[1 * 192 + 2 * 64 + t];
            float r0 = clamp01(bb1[0] - S0);
            float r1 = clamp01(bb2[0] - S1);
            float r2 = clamp01(bb3[0] - S2);
            float acc4 = beta4p[0];
            acc4 -= a40 * (1.f - r0);
            acc4 -= a41 * (1.f - r1);
            acc4 -= a42 * (1.f - r2);
            out[t] = clamp01(acc4);
        }
        if (t == 0) d_ctr = 0;   // reset for next graph replay
    }
}

extern "C" void kernel_launch(void* const* d_in, const int* in_sizes, int n_in,
                              void* d_out, int out_size)
{
    const float* x1      = (const float*)d_in[0];
    const float* x2      = (const float*)d_in[1];
    const float* x3      = (const float*)d_in[2];
    const float* t1      = (const float*)d_in[3];
    const float* b1      = (const float*)d_in[4];
    const float* A1_1    = (const float*)d_in[5];
    const float* A2_1    = (const float*)d_in[6];
    const float* beta1_1 = (const float*)d_in[7];
    const float* beta1_2 = (const float*)d_in[8];
    const float* t2      = (const float*)d_in[9];
    const float* b2      = (const float*)d_in[10];
    const float* A1_2    = (const float*)d_in[11];
    const float* A2_2    = (const float*)d_in[12];
    const float* beta2_1 = (const float*)d_in[13];
    const float* beta2_2 = (const float*)d_in[14];
    const float* t3      = (const float*)d_in[15];
    const float* b3      = (const float*)d_in[16];
    const float* A1_3    = (const float*)d_in[17];
    const float* A2_3    = (const float*)d_in[18];
    const float* beta3_1 = (const float*)d_in[19];
    const float* beta3_2 = (const float*)d_in[20];
    const float* A4      = (const float*)d_in[21];
    const float* beta4   = (const float*)d_in[22];
    float* out = (float*)d_out;

    fused_kernel<<<NBLK, 256>>>(x1, x2, x3,
                                t1, b1, t2, b2, t3, b3,
                                A1_1, A1_2, A1_3,
                                A2_1, A2_2, A2_3,
                                beta1_1, beta2_1, beta3_1,
                                beta1_2, beta2_2, beta3_2,
                                A4, beta4, out);
}